// round 3
// baseline (speedup 1.0000x reference)
#include <cuda_runtime.h>
#include <math.h>

#define KBITS 13
#define NBINS 8192
#define TOPK  2048
#define NPROP 1000
#define MAXB  4

// ---------------- scratch (device globals; no allocation allowed) ----------
__device__ unsigned int       g_hist[MAXB][NBINS];
__device__ unsigned long long g_prefix[MAXB];
__device__ int                g_k[MAXB];
__device__ int                g_cnt[MAXB];
__device__ unsigned long long g_cand[MAXB][TOPK];
__device__ float4             g_boxes[MAXB][TOPK];
__device__ unsigned long long g_mask[MAXB][TOPK * 32];

// ---------------- init: reset all cross-launch state -----------------------
__global__ void init_kernel(int B) {
    int t = blockIdx.x * blockDim.x + threadIdx.x;
    int total = B * NBINS;
    unsigned int* h = (unsigned int*)g_hist;
    for (int i = t; i < total; i += gridDim.x * blockDim.x) h[i] = 0;
    if (t < B) { g_prefix[t] = 0ULL; g_k[t] = TOPK; g_cnt[t] = 0; }
}

// key = (score_bits << 20) | (0xFFFFF - idx)   — unique, ties -> smaller idx wins
__device__ __forceinline__ unsigned long long make_key(unsigned int bits, int i) {
    return ((unsigned long long)bits << 20) |
           (unsigned long long)(0xFFFFFu - (unsigned int)i);
}

// ---------------- radix-select pass: histogram 13 bits under current prefix -
__global__ void radix_pass(const float2* __restrict__ probs, int N, int shift) {
    __shared__ unsigned int sh[NBINS];
    int b = blockIdx.y;
    for (int i = threadIdx.x; i < NBINS; i += blockDim.x) sh[i] = 0;
    __syncthreads();
    unsigned long long prefix = g_prefix[b];
    const float2* p = probs + (size_t)b * N;
    int stride = gridDim.x * blockDim.x;
    for (int i = blockIdx.x * blockDim.x + threadIdx.x; i < N; i += stride) {
        unsigned int bits = __float_as_uint(p[i].y);
        unsigned long long key = make_key(bits, i);
        if ((key >> (shift + KBITS)) == prefix)
            atomicAdd(&sh[(unsigned int)(key >> shift) & (NBINS - 1)], 1u);
    }
    __syncthreads();
    for (int i = threadIdx.x; i < NBINS; i += blockDim.x)
        if (sh[i]) atomicAdd(&g_hist[b][i], sh[i]);
}

// ---------------- resolve one radix digit, reset histogram ------------------
__global__ void radix_resolve() {
    int b = blockIdx.x;
    __shared__ int s_bin, s_k;
    if (threadIdx.x == 0) {
        int k = g_k[b];
        long long cum = 0;
        int bin = 0, kk = 1;
        for (int i = NBINS - 1; i >= 0; i--) {
            int c = (int)g_hist[b][i];
            if (cum + c >= k) { bin = i; kk = k - (int)cum; break; }
            cum += c;
        }
        s_bin = bin; s_k = kk;
    }
    __syncthreads();
    if (threadIdx.x == 0) {
        g_prefix[b] = (g_prefix[b] << KBITS) | (unsigned long long)s_bin;
        g_k[b] = s_k;
    }
    for (int i = threadIdx.x; i < NBINS; i += blockDim.x) g_hist[b][i] = 0;
}

// ---------------- collect exactly TOPK keys >= threshold --------------------
__global__ void collect_kernel(const float2* __restrict__ probs, int N) {
    int b = blockIdx.y;
    unsigned long long T = g_prefix[b];   // full 52-bit threshold key
    const float2* p = probs + (size_t)b * N;
    int stride = gridDim.x * blockDim.x;
    for (int i = blockIdx.x * blockDim.x + threadIdx.x; i < N; i += stride) {
        unsigned int bits = __float_as_uint(p[i].y);
        unsigned long long key = make_key(bits, i);
        if (key >= T) {
            int pos = atomicAdd(&g_cnt[b], 1);
            if (pos < TOPK) g_cand[b][pos] = key;
        }
    }
}

// ---------------- sort 2048 keys (bitonic) + decode boxes -------------------
__global__ void sort_gather(const float4* __restrict__ bbox,
                            const float4* __restrict__ anchors, int N) {
    int b = blockIdx.x;
    int t = threadIdx.x;   // 1024 threads
    __shared__ unsigned long long sk[TOPK];
    sk[t] = g_cand[b][t];
    sk[t + 1024] = g_cand[b][t + 1024];
    __syncthreads();
    for (int k = 2; k <= TOPK; k <<= 1) {
        for (int j = k >> 1; j > 0; j >>= 1) {
            #pragma unroll
            for (int s = 0; s < 2; s++) {
                int i = t + s * 1024;
                int l = i ^ j;
                if (l > i) {
                    bool up = ((i & k) == 0);   // ascending block
                    unsigned long long a = sk[i], c = sk[l];
                    if ((a > c) == up) { sk[i] = c; sk[l] = a; }
                }
            }
            __syncthreads();
        }
    }
    const float4* bb = bbox    + (size_t)b * N;
    const float4* an = anchors + (size_t)b * N;
    #pragma unroll
    for (int s = 0; s < 2; s++) {
        int r = t + s * 1024;                       // rank (descending)
        unsigned long long key = sk[TOPK - 1 - r];
        int idx = 0xFFFFF - (int)(key & 0xFFFFFULL);
        float4 a = an[idx];
        float4 d = bb[idx];
        // deltas = rpn_bbox * [0.1,0.1,0.2,0.2]
        float d0 = __fmul_rn(d.x, 0.1f), d1 = __fmul_rn(d.y, 0.1f);
        float d2 = __fmul_rn(d.z, 0.2f), d3 = __fmul_rn(d.w, 0.2f);
        float h = __fsub_rn(a.z, a.x);
        float w = __fsub_rn(a.w, a.y);
        float cy = __fadd_rn(__fadd_rn(a.x, __fmul_rn(0.5f, h)), __fmul_rn(d0, h));
        float cx = __fadd_rn(__fadd_rn(a.y, __fmul_rn(0.5f, w)), __fmul_rn(d1, w));
        float e2 = (float)exp((double)d2);
        float e3 = (float)exp((double)d3);
        float h2 = __fmul_rn(h, e2);
        float w2 = __fmul_rn(w, e3);
        float y1 = __fsub_rn(cy, __fmul_rn(0.5f, h2));
        float x1 = __fsub_rn(cx, __fmul_rn(0.5f, w2));
        float y2 = __fadd_rn(cy, __fmul_rn(0.5f, h2));
        float x2 = __fadd_rn(cx, __fmul_rn(0.5f, w2));
        y1 = fminf(fmaxf(y1, 0.0f), 1.0f);
        x1 = fminf(fmaxf(x1, 0.0f), 1.0f);
        y2 = fminf(fmaxf(y2, 0.0f), 1.0f);
        x2 = fminf(fmaxf(x2, 0.0f), 1.0f);
        g_boxes[b][r] = make_float4(y1, x1, y2, x2);
    }
}

// ---------------- pairwise IoU > 0.7 bitmask (upper triangle blocks) --------
__global__ void mask_kernel() {
    int b  = blockIdx.z;
    int ib = blockIdx.y;
    int jb = blockIdx.x;
    if (jb < ib) return;
    __shared__ float4 sj[64];
    int t = threadIdx.x;   // 64
    sj[t] = g_boxes[b][jb * 64 + t];
    __syncthreads();
    int i = ib * 64 + t;
    float4 bi = g_boxes[b][i];
    float areai = __fmul_rn(__fsub_rn(bi.z, bi.x), __fsub_rn(bi.w, bi.y));
    unsigned long long bits = 0ULL;
    #pragma unroll 8
    for (int jj = 0; jj < 64; jj++) {
        float4 bj = sj[jj];
        float ih = fmaxf(__fsub_rn(fminf(bi.z, bj.z), fmaxf(bi.x, bj.x)), 0.0f);
        float iw = fmaxf(__fsub_rn(fminf(bi.w, bj.w), fmaxf(bi.y, bj.y)), 0.0f);
        float inter = __fmul_rn(ih, iw);
        float areaj = __fmul_rn(__fsub_rn(bj.z, bj.x), __fsub_rn(bj.w, bj.y));
        float uni = __fsub_rn(__fadd_rn(areai, areaj), inter);
        float iou = __fdiv_rn(inter, __fadd_rn(uni, 1e-8f));
        if (iou > 0.7f) bits |= (1ULL << jj);
    }
    g_mask[b][(size_t)i * 32 + jb] = bits;
}

// ---------------- sequential greedy NMS + emit first 1000 kept --------------
__global__ void nms_kernel(float* __restrict__ out) {
    int b = blockIdx.x;
    int t = threadIdx.x;   // 32 threads (one warp)
    // zero output slab for this batch
    for (int k = t; k < NPROP * 4; k += 32) out[(size_t)b * NPROP * 4 + k] = 0.0f;
    __syncwarp();

    unsigned long long keepw = ~0ULL;   // lane t owns bits [t*64, t*64+64)
    const unsigned long long* mb = g_mask[b];

    for (int c = 0; c < 32; c++) {
        unsigned long long cur = __shfl_sync(0xFFFFFFFFu, keepw, c);
        unsigned long long supp = 0ULL;
        for (int bit = 0; bit < 64; bit++) {
            if ((cur >> bit) & 1ULL) {
                int i = c * 64 + bit;
                // column word for this lane (valid only for word >= c)
                unsigned long long mt = (t > c) ? mb[(size_t)i * 32 + t] : 0ULL;
                // diagonal word (broadcast load, same addr across lanes)
                unsigned long long mc = mb[(size_t)i * 32 + c];
                supp |= mt;
                // suppress only strictly-later bits in this word
                unsigned long long hi = (bit < 63) ? (~0ULL << (bit + 1)) : 0ULL;
                cur &= ~(mc & hi);
            }
        }
        if (t == c)      keepw = cur;
        else if (t > c)  keepw &= ~supp;
    }

    // exclusive prefix of popcounts across lanes
    int pc = __popcll(keepw);
    int ex = pc;
    #pragma unroll
    for (int off = 1; off < 32; off <<= 1) {
        int v = __shfl_up_sync(0xFFFFFFFFu, ex, off);
        if (t >= off) ex += v;
    }
    ex -= pc;

    for (int bit = 0; bit < 64; bit++) {
        if ((keepw >> bit) & 1ULL) {
            unsigned long long lower = (bit > 0) ? (keepw & ((1ULL << bit) - 1ULL)) : 0ULL;
            int rank = ex + __popcll(lower);
            if (rank < NPROP) {
                float4 bx = g_boxes[b][t * 64 + bit];
                float* o = out + ((size_t)b * NPROP + rank) * 4;
                o[0] = bx.x; o[1] = bx.y; o[2] = bx.z; o[3] = bx.w;
            }
        }
    }
}

// ---------------- launch ----------------------------------------------------
extern "C" void kernel_launch(void* const* d_in, const int* in_sizes, int n_in,
                              void* d_out, int out_size) {
    const float2* probs   = (const float2*)d_in[0];  // (B,N,2) f32
    const float4* bbox    = (const float4*)d_in[1];  // (B,N,4) f32
    const float4* anchors = (const float4*)d_in[2];  // (B,N,4) f32
    float* out = (float*)d_out;

    int B = out_size / (NPROP * 4);
    if (B < 1) B = 1;
    if (B > MAXB) B = MAXB;
    int N = in_sizes[0] / (2 * B);

    init_kernel<<<1, 256>>>(B);

    const int shifts[4] = {39, 26, 13, 0};
    for (int p = 0; p < 4; p++) {
        radix_pass<<<dim3(256, B), 256>>>(probs, N, shifts[p]);
        radix_resolve<<<B, 256>>>();
    }

    collect_kernel<<<dim3(256, B), 256>>>(probs, N);
    sort_gather<<<B, 1024>>>(bbox, anchors, N);
    mask_kernel<<<dim3(32, 32, B), 64>>>();
    nms_kernel<<<B, 32>>>(out);
}

// round 4
// speedup vs baseline: 6.3031x; 6.3031x over previous
#include <cuda_runtime.h>
#include <math.h>

#define KBITS 13
#define NBINS 8192
#define TOPK  2048
#define CAND  3072
#define SORTN 4096
#define NPROP 1000
#define MAXB  4
#define TILES 528   // 32*33/2 upper-triangle 64x64 tiles

// ---------------- scratch (device globals; no allocation allowed) ----------
__device__ unsigned int       g_hist[MAXB][NBINS];
__device__ unsigned long long g_prefix[MAXB];
__device__ int                g_k[MAXB];
__device__ int                g_cnt[MAXB];
__device__ unsigned long long g_cand[MAXB][CAND];
__device__ float4             g_boxes[MAXB][TOPK];
__device__ float              g_area[MAXB][TOPK];
__device__ unsigned long long g_mask[MAXB][TOPK * 32];

// ---------------- init: reset all cross-launch state -----------------------
__global__ void init_kernel(int B) {
    int t = blockIdx.x * blockDim.x + threadIdx.x;
    int stride = gridDim.x * blockDim.x;
    unsigned int* h = (unsigned int*)g_hist;
    for (int i = t; i < B * NBINS; i += stride) h[i] = 0;
    unsigned long long* cd = (unsigned long long*)g_cand;
    for (int i = t; i < B * CAND; i += stride) cd[i] = 0ULL;
    if (t < B) { g_prefix[t] = 0ULL; g_k[t] = TOPK; g_cnt[t] = 0; }
}

// key = (score_bits << 20) | (0xFFFFF - idx)   — unique, ties -> smaller idx wins
__device__ __forceinline__ unsigned long long make_key(unsigned int bits, int i) {
    return ((unsigned long long)bits << 20) |
           (unsigned long long)(0xFFFFFu - (unsigned int)i);
}

// ---------------- radix-select pass (float4 = 2 elements per load) ----------
__global__ void radix_pass(const float4* __restrict__ probs4, int N2, int shift) {
    __shared__ unsigned int sh[NBINS];
    int b = blockIdx.y;
    for (int i = threadIdx.x; i < NBINS; i += blockDim.x) sh[i] = 0;
    __syncthreads();
    unsigned long long prefix = g_prefix[b];
    const float4* p = probs4 + (size_t)b * N2;
    int stride = gridDim.x * blockDim.x;
    for (int i = blockIdx.x * blockDim.x + threadIdx.x; i < N2; i += stride) {
        float4 v = __ldg(p + i);
        unsigned long long k0 = make_key(__float_as_uint(v.y), 2 * i);
        unsigned long long k1 = make_key(__float_as_uint(v.w), 2 * i + 1);
        if ((k0 >> (shift + KBITS)) == prefix)
            atomicAdd(&sh[(unsigned int)(k0 >> shift) & (NBINS - 1)], 1u);
        if ((k1 >> (shift + KBITS)) == prefix)
            atomicAdd(&sh[(unsigned int)(k1 >> shift) & (NBINS - 1)], 1u);
    }
    __syncthreads();
    for (int i = threadIdx.x; i < NBINS; i += blockDim.x)
        if (sh[i]) atomicAdd(&g_hist[b][i], sh[i]);
}

// ---------------- parallel resolve: find digit containing the k-th key ------
__global__ void radix_resolve() {
    int b = blockIdx.x;
    int t = threadIdx.x;   // 256
    __shared__ unsigned int s_scan[256];
    __shared__ int s_bin, s_newk;
    // chunk t covers 32 bins descending from (NBINS-1 - 32t)
    int base = NBINS - 1 - t * 32;
    unsigned int cnts[32];
    unsigned int sum = 0;
    #pragma unroll
    for (int m = 0; m < 32; m++) { cnts[m] = g_hist[b][base - m]; sum += cnts[m]; }
    s_scan[t] = sum;
    __syncthreads();
    // Hillis-Steele inclusive scan over chunk sums
    for (int off = 1; off < 256; off <<= 1) {
        unsigned int v = (t >= off) ? s_scan[t - off] : 0u;
        __syncthreads();
        s_scan[t] += v;
        __syncthreads();
    }
    unsigned int k = (unsigned int)g_k[b];
    unsigned int incl = s_scan[t];
    unsigned int excl = incl - sum;
    if (excl < k && k <= incl) {     // exactly one thread
        unsigned int cum = excl;
        #pragma unroll
        for (int m = 0; m < 32; m++) {
            if (cum + cnts[m] >= k) { s_bin = base - m; s_newk = (int)(k - cum); break; }
            cum += cnts[m];
        }
    }
    __syncthreads();
    if (t == 0) {
        g_prefix[b] = (g_prefix[b] << KBITS) | (unsigned long long)s_bin;
        g_k[b] = s_newk;
    }
    #pragma unroll
    for (int m = 0; m < 32; m++) g_hist[b][base - m] = 0;
}

// ---------------- collect all keys whose top-26 bits >= threshold -----------
__global__ void collect_kernel(const float4* __restrict__ probs4, int N2) {
    int b = blockIdx.y;
    unsigned long long T = g_prefix[b];   // 26-bit threshold prefix
    const float4* p = probs4 + (size_t)b * N2;
    int stride = gridDim.x * blockDim.x;
    for (int i = blockIdx.x * blockDim.x + threadIdx.x; i < N2; i += stride) {
        float4 v = __ldg(p + i);
        unsigned long long k0 = make_key(__float_as_uint(v.y), 2 * i);
        unsigned long long k1 = make_key(__float_as_uint(v.w), 2 * i + 1);
        if ((k0 >> 26) >= T) {
            int pos = atomicAdd(&g_cnt[b], 1);
            if (pos < CAND) g_cand[b][pos] = k0;
        }
        if ((k1 >> 26) >= T) {
            int pos = atomicAdd(&g_cnt[b], 1);
            if (pos < CAND) g_cand[b][pos] = k1;
        }
    }
}

// ---------------- sort 4096 keys (bitonic) + take top 2048, decode boxes ----
__global__ void sort_gather(const float4* __restrict__ bbox,
                            const float4* __restrict__ anchors, int N) {
    int b = blockIdx.x;
    int t = threadIdx.x;   // 1024 threads
    __shared__ unsigned long long sk[SORTN];
    #pragma unroll
    for (int s = 0; s < 4; s++) {
        int i = t + s * 1024;
        sk[i] = (i < CAND) ? g_cand[b][i] : 0ULL;
    }
    __syncthreads();
    for (int k = 2; k <= SORTN; k <<= 1) {
        for (int j = k >> 1; j > 0; j >>= 1) {
            #pragma unroll
            for (int s = 0; s < 4; s++) {
                int i = t + s * 1024;
                int l = i ^ j;
                if (l > i) {
                    bool up = ((i & k) == 0);
                    unsigned long long a = sk[i], c = sk[l];
                    if ((a > c) == up) { sk[i] = c; sk[l] = a; }
                }
            }
            __syncthreads();
        }
    }
    const float4* bb = bbox    + (size_t)b * N;
    const float4* an = anchors + (size_t)b * N;
    #pragma unroll
    for (int s = 0; s < 2; s++) {
        int r = t + s * 1024;                       // rank (descending)
        unsigned long long key = sk[SORTN - 1 - r];
        int idx = 0xFFFFF - (int)(key & 0xFFFFFULL);
        float4 a = an[idx];
        float4 d = bb[idx];
        float d0 = __fmul_rn(d.x, 0.1f), d1 = __fmul_rn(d.y, 0.1f);
        float d2 = __fmul_rn(d.z, 0.2f), d3 = __fmul_rn(d.w, 0.2f);
        float h = __fsub_rn(a.z, a.x);
        float w = __fsub_rn(a.w, a.y);
        float cy = __fadd_rn(__fadd_rn(a.x, __fmul_rn(0.5f, h)), __fmul_rn(d0, h));
        float cx = __fadd_rn(__fadd_rn(a.y, __fmul_rn(0.5f, w)), __fmul_rn(d1, w));
        float e2 = (float)exp((double)d2);
        float e3 = (float)exp((double)d3);
        float h2 = __fmul_rn(h, e2);
        float w2 = __fmul_rn(w, e3);
        float y1 = __fsub_rn(cy, __fmul_rn(0.5f, h2));
        float x1 = __fsub_rn(cx, __fmul_rn(0.5f, w2));
        float y2 = __fadd_rn(cy, __fmul_rn(0.5f, h2));
        float x2 = __fadd_rn(cx, __fmul_rn(0.5f, w2));
        y1 = fminf(fmaxf(y1, 0.0f), 1.0f);
        x1 = fminf(fmaxf(x1, 0.0f), 1.0f);
        y2 = fminf(fmaxf(y2, 0.0f), 1.0f);
        x2 = fminf(fmaxf(x2, 0.0f), 1.0f);
        g_boxes[b][r] = make_float4(y1, x1, y2, x2);
        g_area[b][r]  = __fmul_rn(__fsub_rn(y2, y1), __fsub_rn(x2, x1));
    }
}

// ---------------- pairwise IoU > 0.7 bitmask (upper-triangle tiles) ---------
__global__ void mask_kernel() {
    int b = blockIdx.y;
    int tt = blockIdx.x;          // 0..TILES-1 -> (ib, jb) with jb >= ib
    int ib = 0, acc = 0;
    while (acc + (32 - ib) <= tt) { acc += 32 - ib; ib++; }
    int jb = ib + (tt - acc);

    __shared__ float4 sj[64];
    __shared__ float  sa[64];
    int t = threadIdx.x;   // 64
    sj[t] = g_boxes[b][jb * 64 + t];
    sa[t] = g_area[b][jb * 64 + t];
    __syncthreads();
    int i = ib * 64 + t;
    float4 bi = g_boxes[b][i];
    float areai = g_area[b][i];
    unsigned long long bits = 0ULL;
    #pragma unroll 8
    for (int jj = 0; jj < 64; jj++) {
        float4 bj = sj[jj];
        float ih = fmaxf(__fsub_rn(fminf(bi.z, bj.z), fmaxf(bi.x, bj.x)), 0.0f);
        float iw = fmaxf(__fsub_rn(fminf(bi.w, bj.w), fmaxf(bi.y, bj.y)), 0.0f);
        float inter = __fmul_rn(ih, iw);
        float uni = __fsub_rn(__fadd_rn(areai, sa[jj]), inter);
        float den = __fadd_rn(uni, 1e-8f);
        // cheap conservative prefilter: if inter well below 0.7*den, exact iou < 0.7
        if (inter > 0.68f * den) {
            float iou = __fdiv_rn(inter, den);
            if (iou > 0.7f) bits |= (1ULL << jj);
        }
    }
    g_mask[b][(size_t)i * 32 + jb] = bits;
}

// ---------------- sequential greedy NMS (smem-staged) + emit 1000 ----------
#define NMS_T 512
__global__ void nms_kernel(float* __restrict__ out) {
    int b = blockIdx.x;
    int tid = threadIdx.x;   // 512
    __shared__ unsigned long long smask[64][33];   // padded vs bank conflicts
    __shared__ unsigned long long skeep[32];
    __shared__ unsigned long long scur;

    for (int k = tid; k < NPROP * 4; k += NMS_T) out[(size_t)b * NPROP * 4 + k] = 0.0f;
    if (tid < 32) skeep[tid] = ~0ULL;
    __syncthreads();

    const unsigned long long* mb = g_mask[b];
    int warp = tid >> 5, lane = tid & 31;

    for (int c = 0; c < 32; c++) {
        // stage mask rows [c*64, c*64+64) x words [0..31] into smem
        #pragma unroll
        for (int s = 0; s < 4; s++) {
            int k = tid + s * NMS_T;          // 0..2047
            int bit = k >> 5, w = k & 31;
            smask[bit][w] = mb[(size_t)(c * 64 + bit) * 32 + w];
        }
        __syncthreads();

        // serial within-word scan (thread 0); loads are addr-independent LDS
        if (tid == 0) {
            unsigned long long cur = skeep[c];
            #pragma unroll 8
            for (int bit = 0; bit < 64; bit++) {
                if ((cur >> bit) & 1ULL) {
                    unsigned long long hi = (bit < 63) ? (~0ULL << (bit + 1)) : 0ULL;
                    cur &= ~(smask[bit][c] & hi);
                }
            }
            skeep[c] = cur;
            scur = cur;
        }
        __syncthreads();

        // cross-word suppression: warp wi handles words c+1+wi, c+17+wi
        unsigned long long cur = scur;
        for (int w = c + 1 + warp; w < 32; w += 16) {
            unsigned long long m = 0ULL;
            if ((cur >> lane) & 1ULL)        m  = smask[lane][w];
            if ((cur >> (lane + 32)) & 1ULL) m |= smask[lane + 32][w];
            #pragma unroll
            for (int off = 16; off > 0; off >>= 1)
                m |= __shfl_xor_sync(0xFFFFFFFFu, m, off);
            if (lane == 0) skeep[w] &= ~m;
        }
        __syncthreads();
    }

    // emit first NPROP kept boxes (first warp; lane t owns bits [64t, 64t+64))
    if (tid < 32) {
        unsigned long long keepw = skeep[tid];
        int pc = __popcll(keepw);
        int ex = pc;
        #pragma unroll
        for (int off = 1; off < 32; off <<= 1) {
            int v = __shfl_up_sync(0xFFFFFFFFu, ex, off);
            if (tid >= off) ex += v;
        }
        ex -= pc;
        for (int bit = 0; bit < 64; bit++) {
            if ((keepw >> bit) & 1ULL) {
                unsigned long long lower = (bit > 0) ? (keepw & ((1ULL << bit) - 1ULL)) : 0ULL;
                int rank = ex + __popcll(lower);
                if (rank < NPROP) {
                    float4 bx = g_boxes[b][tid * 64 + bit];
                    float* o = out + ((size_t)b * NPROP + rank) * 4;
                    o[0] = bx.x; o[1] = bx.y; o[2] = bx.z; o[3] = bx.w;
                }
            }
        }
    }
}

// ---------------- launch ----------------------------------------------------
extern "C" void kernel_launch(void* const* d_in, const int* in_sizes, int n_in,
                              void* d_out, int out_size) {
    const float4* probs4  = (const float4*)d_in[0];  // (B,N,2) f32 -> 2 elems per float4
    const float4* bbox    = (const float4*)d_in[1];  // (B,N,4) f32
    const float4* anchors = (const float4*)d_in[2];  // (B,N,4) f32
    float* out = (float*)d_out;

    int B = out_size / (NPROP * 4);
    if (B < 1) B = 1;
    if (B > MAXB) B = MAXB;
    int N  = in_sizes[0] / (2 * B);
    int N2 = N / 2;

    init_kernel<<<64, 256>>>(B);

    radix_pass<<<dim3(256, B), 256>>>(probs4, N2, 39);
    radix_resolve<<<B, 256>>>();
    radix_pass<<<dim3(256, B), 256>>>(probs4, N2, 26);
    radix_resolve<<<B, 256>>>();

    collect_kernel<<<dim3(256, B), 256>>>(probs4, N2);
    sort_gather<<<B, 1024>>>(bbox, anchors, N);
    mask_kernel<<<dim3(TILES, B), 64>>>();
    nms_kernel<<<B, NMS_T>>>(out);
}